// round 1
// baseline (speedup 1.0000x reference)
#include <cuda_runtime.h>

#define P_N 96
#define S_N 128
#define HN  8
#define HDN 32
#define LN  16
#define EN  256

// ---------------- scratch (device globals; no allocation allowed) ----------
__device__ float g_q[P_N * LN * EN];      // [p][i][h*32+d], pre-scaled by 1/sqrt(32)
__device__ float g_k[S_N * LN * EN];      // [s][j][h*32+d]
__device__ float g_vw[S_N * HN * LN];     // [s][h][j]
__device__ float g_weff[EN];
__device__ float g_wvf[HN * EN];
__device__ float g_bvf[HN];
__device__ float g_c0;

// ---------------- fold out_proj + output_proj into w_eff, c0 ---------------
__global__ void fold_kernel(const float* __restrict__ Wo, const float* __restrict__ bo,
                            const float* __restrict__ Wop, const float* __restrict__ bop) {
    int e = threadIdx.x;
    float acc = 0.f;
    for (int o = 0; o < EN; ++o) acc = fmaf(Wop[o], Wo[o * EN + e], acc);
    g_weff[e] = acc;
    __shared__ float red[EN];
    red[e] = bo[e] * Wop[e];
    __syncthreads();
    for (int s = 128; s > 0; s >>= 1) {
        if (e < s) red[e] += red[e + s];
        __syncthreads();
    }
    if (e == 0) g_c0 = red[0] + bop[0];
}

// ---------------- fold w_eff into Wv -> Wvf [8,256], bvf[8] ----------------
__global__ void wvf_kernel(const float* __restrict__ in_w, const float* __restrict__ in_b) {
    int e = threadIdx.x;
    for (int h = 0; h < HN; ++h) {
        float acc = 0.f;
        #pragma unroll 4
        for (int d = 0; d < HDN; ++d)
            acc = fmaf(in_w[(2 * EN + h * HDN + d) * EN + e], g_weff[h * HDN + d], acc);
        g_wvf[h * EN + e] = acc;
    }
    if (e < HN) {
        float acc = 0.f;
        for (int d = 0; d < HDN; ++d)
            acc = fmaf(in_b[2 * EN + e * HDN + d], g_weff[e * HDN + d], acc);
        g_bvf[e] = acc;
    }
}

// ---------------- Q / K projection GEMM: out = X @ W^T + b  ----------------
// z = 0: q (pano, 1536 rows, W rows [0,256),  scaled by 1/sqrt(32))
// z = 1: k (sat,  2048 rows, W rows [256,512))
__global__ void __launch_bounds__(256) proj_kernel(const float* __restrict__ pano,
                                                   const float* __restrict__ sat,
                                                   const float* __restrict__ in_w,
                                                   const float* __restrict__ in_b) {
    const int z = blockIdx.z;
    const float* X;
    float* O;
    int rtiles, woff;
    float scale;
    if (z == 0) { X = pano; O = g_q; rtiles = 24; woff = 0;   scale = 0.17677669529663687f; }
    else        { X = sat;  O = g_k; rtiles = 32; woff = EN;  scale = 1.0f; }
    if (blockIdx.x >= rtiles) return;

    const int m0 = blockIdx.x * 64;
    const int n0 = blockIdx.y * 64;

    __shared__ __align__(16) float As[32][68];
    __shared__ __align__(16) float Ws[32][68];

    const int tid = threadIdx.x;
    const int tx = tid & 15, ty = tid >> 4;

    float acc[4][4] = {};

    for (int k0 = 0; k0 < EN; k0 += 32) {
        #pragma unroll
        for (int t = 0; t < 8; ++t) {
            int idx = tid + t * 256;          // 0..2047
            int m = idx >> 5, kk = idx & 31;
            As[kk][m] = X[(m0 + m) * EN + k0 + kk];
            Ws[kk][m] = in_w[(woff + n0 + m) * EN + k0 + kk];
        }
        __syncthreads();
        #pragma unroll
        for (int kk = 0; kk < 32; ++kk) {
            float4 a = *(const float4*)&As[kk][ty * 4];
            float4 b = *(const float4*)&Ws[kk][tx * 4];
            float av[4] = {a.x, a.y, a.z, a.w};
            float bv[4] = {b.x, b.y, b.z, b.w};
            #pragma unroll
            for (int i = 0; i < 4; ++i)
                #pragma unroll
                for (int j = 0; j < 4; ++j)
                    acc[i][j] = fmaf(av[i], bv[j], acc[i][j]);
        }
        __syncthreads();
    }

    #pragma unroll
    for (int i = 0; i < 4; ++i) {
        int row = m0 + ty * 4 + i;
        #pragma unroll
        for (int j = 0; j < 4; ++j) {
            int col = n0 + tx * 4 + j;
            O[row * EN + col] = (acc[i][j] + in_b[woff + col]) * scale;
        }
    }
}

// ---------------- vw[s,h,j] = sat[s,j,:] . Wvf[h,:] + bvf[h] ---------------
__global__ void __launch_bounds__(256) vw_kernel(const float* __restrict__ sat) {
    __shared__ __align__(16) float wv[HN * EN];
    __shared__ float bv[HN];
    const int tid = threadIdx.x;
    for (int t = tid; t < HN * EN; t += 256) wv[t] = g_wvf[t];
    if (tid < HN) bv[tid] = g_bvf[tid];
    __syncthreads();

    const int r = blockIdx.x * 32 + (tid >> 3);   // row in [0, 2048)
    const int h = tid & 7;
    const float4* x = (const float4*)(sat + r * EN);
    const float4* w = (const float4*)(wv + h * EN);
    float acc = bv[h];
    #pragma unroll 8
    for (int e4 = 0; e4 < EN / 4; ++e4) {
        float4 a = x[e4], b = w[e4];
        acc = fmaf(a.x, b.x, acc);
        acc = fmaf(a.y, b.y, acc);
        acc = fmaf(a.z, b.z, acc);
        acc = fmaf(a.w, b.w, acc);
    }
    int s = r >> 4, j = r & 15;
    g_vw[s * (HN * LN) + h * LN + j] = acc;
}

// ---------------- fused attention + fold-dot kernel ------------------------
// grid = (32, 96): block handles 1 pano x 4 sats. 128 threads, warp -> sat.
// lane = h*4 + ic : owns i in {ic*4..ic*4+3}, all 16 j, for head h.
#define QI 36          // q i-stride (words)
#define QH 580         // q h-stride (words), 580 mod 32 = 4
#define QSZ 4640       // 8 * 580
#define KH 516         // k h-stride (words), 516 mod 32 = 4
#define KSAT 4128      // 8 * 516
#define KBASE QSZ
#define VWBASE (QSZ + 4 * KSAT)        // 21152
#define SMEM_WORDS (VWBASE + 4 * HN * LN)   // 21664
#define SMEM_BYTES (SMEM_WORDS * 4)         // 86656

__global__ void __launch_bounds__(128) attn_kernel(float* __restrict__ out) {
    extern __shared__ float sm[];
    const int tid = threadIdx.x;
    const int p = blockIdx.y;
    const int s0 = blockIdx.x * 4;

    // ---- stage Q [16 x 256] with per-h padding + chunk XOR swizzle ----
    for (int idx = tid; idx < LN * EN; idx += 128) {
        int i = idx >> 8, e = idx & 255;
        int h = e >> 5, d = e & 31;
        int c = (d >> 2) ^ ((i >> 2) & 3);          // chunk swizzle
        sm[h * QH + i * QI + (c << 2) + (d & 3)] = g_q[(p * LN + i) * EN + e];
    }
    // ---- stage K for 4 sats ----
    for (int idx = tid; idx < 4 * LN * EN; idx += 128) {
        int sat = idx >> 12, rem = idx & 4095;
        int j = rem >> 8, e = rem & 255;
        int h = e >> 5, d = e & 31;
        sm[KBASE + sat * KSAT + h * KH + j * 32 + d] = g_k[((s0 + sat) * LN + j) * EN + e];
    }
    // ---- stage vw ----
    for (int idx = tid; idx < 4 * HN * LN; idx += 128)
        sm[VWBASE + idx] = g_vw[s0 * (HN * LN) + idx];
    __syncthreads();

    const int w = tid >> 5;           // sat within block
    const int lane = tid & 31;
    const int h = lane >> 2;
    const int ic = lane & 3;

    const float* qb = sm + h * QH;
    const float* kb = sm + KBASE + w * KSAT + h * KH;

    float acc[4][16];
    #pragma unroll
    for (int rr = 0; rr < 4; ++rr)
        #pragma unroll
        for (int j = 0; j < 16; ++j) acc[rr][j] = 0.f;

    for (int d4 = 0; d4 < 32; d4 += 4) {
        const int dd = d4 >> 2;
        float4 q4[4];
        #pragma unroll
        for (int rr = 0; rr < 4; ++rr) {
            int i = ic * 4 + rr;
            q4[rr] = *(const float4*)(qb + i * QI + ((dd ^ ic) << 2));
        }
        #pragma unroll
        for (int j = 0; j < 16; ++j) {
            float4 k4 = *(const float4*)(kb + j * 32 + d4);
            #pragma unroll
            for (int rr = 0; rr < 4; ++rr) {
                acc[rr][j] = fmaf(q4[rr].x, k4.x, acc[rr][j]);
                acc[rr][j] = fmaf(q4[rr].y, k4.y, acc[rr][j]);
                acc[rr][j] = fmaf(q4[rr].z, k4.z, acc[rr][j]);
                acc[rr][j] = fmaf(q4[rr].w, k4.w, acc[rr][j]);
            }
        }
    }

    // ---- softmax over j (16) fused with vw dot; scores already scaled via q ----
    const float* vwb = sm + VWBASE + w * (HN * LN) + h * LN;
    float lane_sum = 0.f;
    #pragma unroll
    for (int rr = 0; rr < 4; ++rr) {
        float num = 0.f, den = 0.f;
        #pragma unroll
        for (int j = 0; j < 16; ++j) {
            float e = __expf(acc[rr][j]);
            num = fmaf(e, vwb[j], num);
            den += e;
        }
        lane_sum += __fdividef(num, den);
    }
    #pragma unroll
    for (int off = 16; off > 0; off >>= 1)
        lane_sum += __shfl_xor_sync(0xffffffffu, lane_sum, off);

    if (lane == 0)
        out[p * S_N + (s0 + w)] = lane_sum * (1.f / 16.f) + g_c0;
}

// ---------------- launch ---------------------------------------------------
extern "C" void kernel_launch(void* const* d_in, const int* in_sizes, int n_in,
                              void* d_out, int out_size) {
    const float* sat   = (const float*)d_in[0];
    const float* pano  = (const float*)d_in[1];
    const float* in_w  = (const float*)d_in[2];
    const float* in_b  = (const float*)d_in[3];
    const float* out_w = (const float*)d_in[4];
    const float* out_b = (const float*)d_in[5];
    const float* op_w  = (const float*)d_in[6];
    const float* op_b  = (const float*)d_in[7];
    float* out = (float*)d_out;

    cudaFuncSetAttribute(attn_kernel, cudaFuncAttributeMaxDynamicSharedMemorySize, SMEM_BYTES);

    fold_kernel<<<1, 256>>>(out_w, out_b, op_w, op_b);
    wvf_kernel<<<1, 256>>>(in_w, in_b);
    proj_kernel<<<dim3(32, 4, 2), 256>>>(pano, sat, in_w, in_b);
    vw_kernel<<<64, 256>>>(sat);
    attn_kernel<<<dim3(32, 96), 128, SMEM_BYTES>>>(out);
}

// round 3
// speedup vs baseline: 1.9695x; 1.9695x over previous
#include <cuda_runtime.h>

#define P_N 96
#define S_N 128
#define HN  8
#define HDN 32
#define LN  16
#define EN  256

// ---------------- scratch (device globals; no allocation allowed) ----------
// g_q: [p][h][i][32] words, chunk-XOR swizzled in d, pre-scaled by 1/sqrt(32)
// g_k: [s][h][j][32] words, plain
__device__ float g_q[P_N * LN * EN];
__device__ float g_k[S_N * LN * EN];
__device__ float g_vw[S_N * HN * LN];     // [s][h][j]
__device__ float g_wvf[HN * EN];          // [h][e]
__device__ float g_bvf[HN];
__device__ float g_c0;

// ---------------- prep: weff (per-head slice), Wvf, bvf, c0 ----------------
// grid = 8 blocks (one per head), 256 threads.
__global__ void __launch_bounds__(256) prep_kernel(
        const float* __restrict__ in_w, const float* __restrict__ in_b,
        const float* __restrict__ Wo,   const float* __restrict__ bo,
        const float* __restrict__ Wop,  const float* __restrict__ bop) {
    const int h = blockIdx.x;
    const int tid = threadIdx.x;
    __shared__ float sweff[HDN];

    // weff[h*32+d] = sum_o Wop[o] * Wo[o][h*32+d]; 8 partial lanes per d.
    {
        int d = tid >> 3, part = tid & 7;
        float a = 0.f;
        int obase = part * 32;
        #pragma unroll 8
        for (int o = 0; o < 32; ++o)
            a = fmaf(Wop[obase + o], Wo[(obase + o) * EN + h * HDN + d], a);
        a += __shfl_xor_sync(0xffffffffu, a, 1);
        a += __shfl_xor_sync(0xffffffffu, a, 2);
        a += __shfl_xor_sync(0xffffffffu, a, 4);
        if (part == 0) sweff[d] = a;
    }
    __syncthreads();

    // Wvf[h][e] = sum_d Wv[h*32+d][e] * weff[h*32+d]
    {
        int e = tid;
        float acc = 0.f;
        #pragma unroll 8
        for (int d = 0; d < HDN; ++d)
            acc = fmaf(in_w[(2 * EN + h * HDN + d) * EN + e], sweff[d], acc);
        g_wvf[h * EN + e] = acc;
    }
    // bvf[h]
    if (tid < 32) {
        float b = in_b[2 * EN + h * HDN + tid] * sweff[tid];
        #pragma unroll
        for (int off = 16; off > 0; off >>= 1)
            b += __shfl_xor_sync(0xffffffffu, b, off);
        if (tid == 0) g_bvf[h] = b;
    }
    // c0 (block 0 only)
    if (h == 0) {
        __shared__ float red[EN];
        red[tid] = bo[tid] * Wop[tid];
        __syncthreads();
        for (int s = 128; s > 0; s >>= 1) {
            if (tid < s) red[tid] += red[tid + s];
            __syncthreads();
        }
        if (tid == 0) g_c0 = red[0] + bop[0];
    }
}

// ---------------- Q / K projection GEMM with layout-permuting epilogue -----
__global__ void __launch_bounds__(256) proj_kernel(const float* __restrict__ pano,
                                                   const float* __restrict__ sat,
                                                   const float* __restrict__ in_w,
                                                   const float* __restrict__ in_b) {
    const int z = blockIdx.z;
    const float* X;
    int rtiles, woff;
    if (z == 0) { X = pano; rtiles = 24; woff = 0;  }
    else        { X = sat;  rtiles = 32; woff = EN; }
    if (blockIdx.x >= rtiles) return;

    const int m0 = blockIdx.x * 64;
    const int n0 = blockIdx.y * 64;

    __shared__ __align__(16) float As[32][68];
    __shared__ __align__(16) float Ws[32][68];

    const int tid = threadIdx.x;
    const int tx = tid & 15, ty = tid >> 4;

    float acc[4][4] = {};

    for (int k0 = 0; k0 < EN; k0 += 32) {
        #pragma unroll
        for (int t = 0; t < 8; ++t) {
            int idx = tid + t * 256;
            int m = idx >> 5, kk = idx & 31;
            As[kk][m] = X[(m0 + m) * EN + k0 + kk];
            Ws[kk][m] = in_w[(woff + n0 + m) * EN + k0 + kk];
        }
        __syncthreads();
        #pragma unroll
        for (int kk = 0; kk < 32; ++kk) {
            float4 a = *(const float4*)&As[kk][ty * 4];
            float4 b = *(const float4*)&Ws[kk][tx * 4];
            float av[4] = {a.x, a.y, a.z, a.w};
            float bv[4] = {b.x, b.y, b.z, b.w};
            #pragma unroll
            for (int i = 0; i < 4; ++i)
                #pragma unroll
                for (int j = 0; j < 4; ++j)
                    acc[i][j] = fmaf(av[i], bv[j], acc[i][j]);
        }
        __syncthreads();
    }

    #pragma unroll
    for (int i = 0; i < 4; ++i) {
        int row = m0 + ty * 4 + i;              // p*16+i  or  s*16+j
        int rr = row >> 4, ri = row & 15;
        #pragma unroll
        for (int j = 0; j < 4; ++j) {
            int col = n0 + tx * 4 + j;          // h*32+d
            int h = col >> 5, d = col & 31;
            float v = acc[i][j] + in_b[woff + col];
            if (z == 0) {
                int c = (d >> 2) ^ ((ri >> 2) & 3);  // chunk swizzle for Q
                g_q[((rr * HN + h) * LN + ri) * 32 + (c << 2) + (d & 3)]
                    = v * 0.17677669529663687f;
            } else {
                g_k[((rr * HN + h) * LN + ri) * 32 + d] = v;
            }
        }
    }
}

// ---------------- vw[s,h,j] = sat[s,j,:] . Wvf[h,:] + bvf[h] ---------------
// split-K x4: thread = (row r, head h, quarter q). 256 blocks x 256 threads.
__global__ void __launch_bounds__(256) vw_kernel(const float* __restrict__ sat) {
    const int T = blockIdx.x * 256 + threadIdx.x;
    const int q = T & 3;
    const int h = (T >> 2) & 7;
    const int r = T >> 5;                       // 0..2047
    const float4* __restrict__ x = (const float4*)(sat + r * EN + q * 64);
    const float4* __restrict__ w = (const float4*)(g_wvf + h * EN + q * 64);
    float acc = 0.f;
    #pragma unroll
    for (int e4 = 0; e4 < 16; ++e4) {
        float4 a = __ldg(x + e4), b = __ldg(w + e4);
        acc = fmaf(a.x, b.x, acc);
        acc = fmaf(a.y, b.y, acc);
        acc = fmaf(a.z, b.z, acc);
        acc = fmaf(a.w, b.w, acc);
    }
    acc += __shfl_xor_sync(0xffffffffu, acc, 1);
    acc += __shfl_xor_sync(0xffffffffu, acc, 2);
    if (q == 0) {
        int s = r >> 4, j = r & 15;
        g_vw[s * (HN * LN) + h * LN + j] = acc + __ldg(g_bvf + h);
    }
}

// ---------------- fused attention + fold-dot kernel ------------------------
// grid = (32 satgroups, 48 pano-pairs). Block: 4 sats x 2 panos, 128 threads.
// warp w -> sat; lane: h = lane&7, ic = lane>>3 (4 i-rows each).
#define QH 580                      // q h-stride (words)
#define QP 4640                     // q pano-stride (words) = 8*580
#define KH 516                      // k h-stride (words)
#define KSAT 4128                   // 8*516
#define KBASE (2 * QP)              // 9280
#define VWBASE (KBASE + 4 * KSAT)   // 25792
#define VWH 20                      // vw h-stride (words)
#define VWSAT 160                   // 8*20
#define SMEM_WORDS (VWBASE + 4 * VWSAT)     // 26432
#define SMEM_BYTES (SMEM_WORDS * 4)         // 105728

__global__ void __launch_bounds__(128) attn_kernel(float* __restrict__ out) {
    extern __shared__ float sm[];
    float4* sm4 = (float4*)sm;
    const int tid = threadIdx.x;
    const int p0 = blockIdx.y * 2;
    const int s0 = blockIdx.x * 4;
    const float c0 = g_c0;

    // ---- stage Q (2 panos): pure float4 copy, layout already swizzled ----
    {
        const float4* __restrict__ src = (const float4*)g_q + p0 * 1024;
        #pragma unroll
        for (int t = 0; t < 16; ++t) {
            int u = tid + t * 128;               // 0..2047
            int rem = u & 1023;                  // h*128 + i*8 + c
            int h = rem >> 7, i = (rem >> 3) & 15;
            sm4[(u >> 10) * 1160 + rem + h * 17 + i] = src[u];
        }
    }
    // ---- stage K (4 sats) ----
    {
        const float4* __restrict__ src = (const float4*)g_k + s0 * 1024;
        #pragma unroll
        for (int t = 0; t < 32; ++t) {
            int u = tid + t * 128;               // 0..4095
            int rem = u & 1023;
            int h = rem >> 7;
            sm4[(KBASE >> 2) + (u >> 10) * 1032 + rem + h] = src[u];
        }
    }
    // ---- stage vw ----
    {
        const float* __restrict__ src = g_vw + s0 * (HN * LN);
        #pragma unroll
        for (int t = 0; t < 4; ++t) {
            int u = tid + t * 128;               // 0..511
            int rem = u & 127;                   // h*16 + j
            int h = rem >> 4, j = rem & 15;
            sm[VWBASE + (u >> 7) * VWSAT + h * VWH + j] = src[u];
        }
    }
    __syncthreads();

    const int w = tid >> 5;                      // sat within block
    const int lane = tid & 31;
    const int h = lane & 7;
    const int ic = lane >> 3;

    const float* kb = sm + KBASE + w * KSAT + h * KH;
    const float* vwb = sm + VWBASE + w * VWSAT + h * VWH;

    for (int pl = 0; pl < 2; ++pl) {
        const float* qb = sm + pl * QP + h * QH;

        float acc[4][16];
        #pragma unroll
        for (int rr = 0; rr < 4; ++rr)
            #pragma unroll
            for (int j = 0; j < 16; ++j) acc[rr][j] = 0.f;

        for (int d4 = 0; d4 < 32; d4 += 4) {
            const int dd = d4 >> 2;
            float4 q4[4];
            #pragma unroll
            for (int rr = 0; rr < 4; ++rr)
                q4[rr] = *(const float4*)(qb + (ic * 4 + rr) * 36 + ((dd ^ ic) << 2));
            #pragma unroll
            for (int j = 0; j < 16; ++j) {
                float4 k4 = *(const float4*)(kb + j * 32 + d4);
                #pragma unroll
                for (int rr = 0; rr < 4; ++rr) {
                    acc[rr][j] = fmaf(q4[rr].x, k4.x, acc[rr][j]);
                    acc[rr][j] = fmaf(q4[rr].y, k4.y, acc[rr][j]);
                    acc[rr][j] = fmaf(q4[rr].z, k4.z, acc[rr][j]);
                    acc[rr][j] = fmaf(q4[rr].w, k4.w, acc[rr][j]);
                }
            }
        }

        // softmax over j fused with vw dot (scores pre-scaled via q)
        float lane_sum = 0.f;
        #pragma unroll
        for (int rr = 0; rr < 4; ++rr) {
            float num = 0.f, den = 0.f;
            #pragma unroll
            for (int j = 0; j < 16; ++j) {
                float e = __expf(acc[rr][j]);
                num = fmaf(e, vwb[j], num);
                den += e;
            }
            lane_sum += __fdividef(num, den);
        }
        #pragma unroll
        for (int off = 16; off > 0; off >>= 1)
            lane_sum += __shfl_xor_sync(0xffffffffu, lane_sum, off);

        if (lane == 0)
            out[(p0 + pl) * S_N + (s0 + w)] = lane_sum * (1.f / 16.f) + c0;
    }
}

// ---------------- launch ---------------------------------------------------
extern "C" void kernel_launch(void* const* d_in, const int* in_sizes, int n_in,
                              void* d_out, int out_size) {
    const float* sat   = (const float*)d_in[0];
    const float* pano  = (const float*)d_in[1];
    const float* in_w  = (const float*)d_in[2];
    const float* in_b  = (const float*)d_in[3];
    const float* out_w = (const float*)d_in[4];
    const float* out_b = (const float*)d_in[5];
    const float* op_w  = (const float*)d_in[6];
    const float* op_b  = (const float*)d_in[7];
    float* out = (float*)d_out;

    cudaFuncSetAttribute(attn_kernel, cudaFuncAttributeMaxDynamicSharedMemorySize, SMEM_BYTES);

    prep_kernel<<<8, 256>>>(in_w, in_b, out_w, out_b, op_w, op_b);
    proj_kernel<<<dim3(32, 4, 2), 256>>>(pano, sat, in_w, in_b);
    vw_kernel<<<256, 256>>>(sat);
    attn_kernel<<<dim3(32, 48), 128, SMEM_BYTES>>>(out);
}

// round 4
// speedup vs baseline: 2.1451x; 1.0892x over previous
#include <cuda_runtime.h>

#define P_N 96
#define S_N 128
#define HN  8
#define HDN 32
#define LN  16
#define EN  256

typedef unsigned long long u64;

__device__ __forceinline__ u64 fma2(u64 a, u64 b, u64 c) {
    u64 d;
    asm("fma.rn.f32x2 %0, %1, %2, %3;" : "=l"(d) : "l"(a), "l"(b), "l"(c));
    return d;
}
__device__ __forceinline__ u64 pack2(float x) {
    u64 d;
    unsigned r = __float_as_uint(x);
    asm("mov.b64 %0, {%1, %1};" : "=l"(d) : "r"(r));
    return d;
}

// ---------------- scratch (device globals; no allocation allowed) ----------
// g_q : [p][h][i][32] words, chunk-XOR swizzled in d, pre-scaled by 1/sqrt(32)
// g_k : [s][h][j][32] words (proj output)
// g_kt: [s][h][d][j16] words (transposed for f32x2 j-packing)
__device__ float g_q[P_N * LN * EN];
__device__ float g_k[S_N * LN * EN];
__device__ float g_kt[S_N * LN * EN];
__device__ float g_vw[S_N * HN * LN];     // [s][h][j]
__device__ float g_wvf[HN * EN];          // [h][e]
__device__ float g_bvf[HN];
__device__ float g_c0;

// ---------------- prep: weff (per-head slice), Wvf, bvf, c0 ----------------
__global__ void __launch_bounds__(256) prep_kernel(
        const float* __restrict__ in_w, const float* __restrict__ in_b,
        const float* __restrict__ Wo,   const float* __restrict__ bo,
        const float* __restrict__ Wop,  const float* __restrict__ bop) {
    const int h = blockIdx.x;
    const int tid = threadIdx.x;
    __shared__ float sweff[HDN];

    {
        int d = tid >> 3, part = tid & 7;
        float a = 0.f;
        int obase = part * 32;
        #pragma unroll 8
        for (int o = 0; o < 32; ++o)
            a = fmaf(Wop[obase + o], Wo[(obase + o) * EN + h * HDN + d], a);
        a += __shfl_xor_sync(0xffffffffu, a, 1);
        a += __shfl_xor_sync(0xffffffffu, a, 2);
        a += __shfl_xor_sync(0xffffffffu, a, 4);
        if (part == 0) sweff[d] = a;
    }
    __syncthreads();

    {
        int e = tid;
        float acc = 0.f;
        #pragma unroll 8
        for (int d = 0; d < HDN; ++d)
            acc = fmaf(in_w[(2 * EN + h * HDN + d) * EN + e], sweff[d], acc);
        g_wvf[h * EN + e] = acc;
    }
    if (tid < 32) {
        float b = in_b[2 * EN + h * HDN + tid] * sweff[tid];
        #pragma unroll
        for (int off = 16; off > 0; off >>= 1)
            b += __shfl_xor_sync(0xffffffffu, b, off);
        if (tid == 0) g_bvf[h] = b;
    }
    if (h == 0) {
        __shared__ float red[EN];
        red[tid] = bo[tid] * Wop[tid];
        __syncthreads();
        for (int s = 128; s > 0; s >>= 1) {
            if (tid < s) red[tid] += red[tid + s];
            __syncthreads();
        }
        if (tid == 0) g_c0 = red[0] + bop[0];
    }
}

// ---------------- Q / K projection GEMM (f32x2) ----------------------------
__global__ void __launch_bounds__(256) proj_kernel(const float* __restrict__ pano,
                                                   const float* __restrict__ sat,
                                                   const float* __restrict__ in_w,
                                                   const float* __restrict__ in_b) {
    const int z = blockIdx.z;
    const float* X;
    int rtiles, woff;
    if (z == 0) { X = pano; rtiles = 24; woff = 0;  }
    else        { X = sat;  rtiles = 32; woff = EN; }
    if (blockIdx.x >= rtiles) return;

    const int m0 = blockIdx.x * 64;
    const int n0 = blockIdx.y * 64;

    __shared__ __align__(16) float As[32][68];
    __shared__ __align__(16) float Ws[32][68];

    const int tid = threadIdx.x;
    const int tx = tid & 15, ty = tid >> 4;

    u64 acc2[4][2];
    #pragma unroll
    for (int i = 0; i < 4; ++i) { acc2[i][0] = 0ull; acc2[i][1] = 0ull; }

    for (int k0 = 0; k0 < EN; k0 += 32) {
        #pragma unroll
        for (int t = 0; t < 8; ++t) {
            int idx = tid + t * 256;
            int m = idx >> 5, kk = idx & 31;
            As[kk][m] = X[(m0 + m) * EN + k0 + kk];
            Ws[kk][m] = in_w[(woff + n0 + m) * EN + k0 + kk];
        }
        __syncthreads();
        #pragma unroll
        for (int kk = 0; kk < 32; ++kk) {
            float4 a = *(const float4*)&As[kk][ty * 4];
            ulonglong2 b2 = *(const ulonglong2*)&Ws[kk][tx * 4];
            const float av[4] = {a.x, a.y, a.z, a.w};
            #pragma unroll
            for (int i = 0; i < 4; ++i) {
                u64 aq = pack2(av[i]);
                acc2[i][0] = fma2(aq, b2.x, acc2[i][0]);
                acc2[i][1] = fma2(aq, b2.y, acc2[i][1]);
            }
        }
        __syncthreads();
    }

    #pragma unroll
    for (int i = 0; i < 4; ++i) {
        int row = m0 + ty * 4 + i;              // p*16+i  or  s*16+j
        int rr = row >> 4, ri = row & 15;
        #pragma unroll
        for (int jp = 0; jp < 2; ++jp) {
            float2 v2 = *(float2*)&acc2[i][jp];
            const float vv[2] = {v2.x, v2.y};
            #pragma unroll
            for (int half = 0; half < 2; ++half) {
                int col = n0 + tx * 4 + jp * 2 + half;   // h*32+d
                int h = col >> 5, d = col & 31;
                float v = vv[half] + in_b[woff + col];
                if (z == 0) {
                    int c = (d >> 2) ^ ((ri >> 2) & 3);  // chunk swizzle for Q
                    g_q[((rr * HN + h) * LN + ri) * 32 + (c << 2) + (d & 3)]
                        = v * 0.17677669529663687f;
                } else {
                    g_k[((rr * HN + h) * LN + ri) * 32 + d] = v;
                }
            }
        }
    }
}

// ---------------- K transpose: g_k [s][h][j][32] -> g_kt [s][h][d][j16] ----
__global__ void __launch_bounds__(128) kt_kernel() {
    __shared__ __align__(16) float st[HN * 528];   // [h][j][33]
    const int s = blockIdx.x;
    const int tid = threadIdx.x;
    const float4* __restrict__ src = (const float4*)g_k + s * 1024;
    #pragma unroll
    for (int kq = 0; kq < 8; ++kq) {
        int u = tid + kq * 128;                    // h*128 + j*8 + dc
        float4 v = src[u];
        int h = u >> 7, j = (u >> 3) & 15, dc = u & 7;
        float* dst = st + h * 528 + j * 33 + dc * 4;
        dst[0] = v.x; dst[1] = v.y; dst[2] = v.z; dst[3] = v.w;
    }
    __syncthreads();
    float4* __restrict__ out = (float4*)g_kt + s * 1024;
    const int h = tid >> 4;
    #pragma unroll
    for (int half = 0; half < 2; ++half) {
        int d = (tid & 15) + half * 16;
        const float* row = st + h * 528 + d;
        #pragma unroll
        for (int m = 0; m < 4; ++m) {
            float4 v;
            v.x = row[(4 * m + 0) * 33];
            v.y = row[(4 * m + 1) * 33];
            v.z = row[(4 * m + 2) * 33];
            v.w = row[(4 * m + 3) * 33];
            out[(h * 512 + d * 16) >> 2 | m] = v;   // (h*512+d*16)/4 + m
        }
    }
}

// ---------------- vw[s,h,j] = sat[s,j,:] . Wvf[h,:] + bvf[h] ---------------
__global__ void __launch_bounds__(256) vw_kernel(const float* __restrict__ sat) {
    const int T = blockIdx.x * 256 + threadIdx.x;
    const int q = T & 3;
    const int h = (T >> 2) & 7;
    const int r = T >> 5;                       // 0..2047
    const float4* __restrict__ x = (const float4*)(sat + r * EN + q * 64);
    const float4* __restrict__ w = (const float4*)(g_wvf + h * EN + q * 64);
    float acc = 0.f;
    #pragma unroll
    for (int e4 = 0; e4 < 16; ++e4) {
        float4 a = __ldg(x + e4), b = __ldg(w + e4);
        acc = fmaf(a.x, b.x, acc);
        acc = fmaf(a.y, b.y, acc);
        acc = fmaf(a.z, b.z, acc);
        acc = fmaf(a.w, b.w, acc);
    }
    acc += __shfl_xor_sync(0xffffffffu, acc, 1);
    acc += __shfl_xor_sync(0xffffffffu, acc, 2);
    if (q == 0) {
        int s = r >> 4, j = r & 15;
        g_vw[s * (HN * LN) + h * LN + j] = acc + __ldg(g_bvf + h);
    }
}

// ---------------- fused attention + fold-dot kernel (f32x2) ----------------
// grid = (32 satgroups, 48 pano-pairs). Block: 4 sats x 2 panos, 128 threads.
// warp w -> sat; lane: h = lane&7, ic = lane>>3 (4 i-rows each).
#define QH 580                      // q h-stride (words)
#define QP 4640                     // q pano-stride (words) = 8*580
#define KH 516                      // kt h-stride (words): [d][j16] inside
#define KSAT 4128                   // 8*516
#define KBASE (2 * QP)              // 9280
#define VWBASE (KBASE + 4 * KSAT)   // 25792
#define VWH 20                      // vw h-stride (words)
#define VWSAT 160                   // 8*20
#define SMEM_WORDS (VWBASE + 4 * VWSAT)     // 26432
#define SMEM_BYTES (SMEM_WORDS * 4)         // 105728

__global__ void __launch_bounds__(128) attn_kernel(float* __restrict__ out) {
    extern __shared__ float sm[];
    float4* sm4 = (float4*)sm;
    const int tid = threadIdx.x;
    const int p0 = blockIdx.y * 2;
    const int s0 = blockIdx.x * 4;
    const float c0 = g_c0;

    // ---- stage Q (2 panos): pure float4 copy, layout already swizzled ----
    {
        const float4* __restrict__ src = (const float4*)g_q + p0 * 1024;
        #pragma unroll
        for (int t = 0; t < 16; ++t) {
            int u = tid + t * 128;               // 0..2047
            int rem = u & 1023;                  // h*128 + i*8 + c
            int h = rem >> 7, i = (rem >> 3) & 15;
            sm4[(u >> 10) * 1160 + rem + h * 17 + i] = src[u];
        }
    }
    // ---- stage Kt (4 sats): [h][d][j16], pad 4 words per h ----
    {
        const float4* __restrict__ src = (const float4*)g_kt + s0 * 1024;
        #pragma unroll
        for (int t = 0; t < 32; ++t) {
            int u = tid + t * 128;               // 0..4095
            int rem = u & 1023;
            int h = rem >> 7;
            sm4[(KBASE >> 2) + (u >> 10) * 1032 + rem + h] = src[u];
        }
    }
    // ---- stage vw ----
    {
        const float* __restrict__ src = g_vw + s0 * (HN * LN);
        #pragma unroll
        for (int t = 0; t < 4; ++t) {
            int u = tid + t * 128;               // 0..511
            int rem = u & 127;                   // h*16 + j
            int h = rem >> 4, j = rem & 15;
            sm[VWBASE + (u >> 7) * VWSAT + h * VWH + j] = src[u];
        }
    }
    __syncthreads();

    const int w = tid >> 5;                      // sat within block
    const int lane = tid & 31;
    const int h = lane & 7;
    const int ic = lane >> 3;

    const float* kb = sm + KBASE + w * KSAT + h * KH;   // [d][j16]
    const float* vwb = sm + VWBASE + w * VWSAT + h * VWH;

    for (int pl = 0; pl < 2; ++pl) {
        const float* qb = sm + pl * QP + h * QH;

        u64 acc2[4][8];
        #pragma unroll
        for (int rr = 0; rr < 4; ++rr)
            #pragma unroll
            for (int jp = 0; jp < 8; ++jp) acc2[rr][jp] = 0ull;

        for (int d4 = 0; d4 < 32; d4 += 4) {
            const int dd4 = d4 >> 2;
            float4 q4[4];
            #pragma unroll
            for (int rr = 0; rr < 4; ++rr)
                q4[rr] = *(const float4*)(qb + (ic * 4 + rr) * 36 + ((dd4 ^ ic) << 2));
            #pragma unroll
            for (int t = 0; t < 4; ++t) {
                const float* kd = kb + (d4 + t) * 16;
                ulonglong2 kv0 = *(const ulonglong2*)(kd);
                ulonglong2 kv1 = *(const ulonglong2*)(kd + 4);
                ulonglong2 kv2 = *(const ulonglong2*)(kd + 8);
                ulonglong2 kv3 = *(const ulonglong2*)(kd + 12);
                const u64 kp[8] = {kv0.x, kv0.y, kv1.x, kv1.y,
                                   kv2.x, kv2.y, kv3.x, kv3.y};
                #pragma unroll
                for (int rr = 0; rr < 4; ++rr) {
                    const float qv[4] = {q4[rr].x, q4[rr].y, q4[rr].z, q4[rr].w};
                    u64 qq = pack2(qv[t]);
                    #pragma unroll
                    for (int jp = 0; jp < 8; ++jp)
                        acc2[rr][jp] = fma2(qq, kp[jp], acc2[rr][jp]);
                }
            }
        }

        // softmax over j fused with vw dot (scores pre-scaled via q)
        float lane_sum = 0.f;
        #pragma unroll
        for (int rr = 0; rr < 4; ++rr) {
            float num = 0.f, den = 0.f;
            #pragma unroll
            for (int jp = 0; jp < 8; ++jp) {
                float2 v2 = *(float2*)&acc2[rr][jp];
                float e0 = __expf(v2.x);
                float e1 = __expf(v2.y);
                num = fmaf(e0, vwb[jp * 2], num);
                num = fmaf(e1, vwb[jp * 2 + 1], num);
                den += e0 + e1;
            }
            lane_sum += __fdividef(num, den);
        }
        #pragma unroll
        for (int off = 16; off > 0; off >>= 1)
            lane_sum += __shfl_xor_sync(0xffffffffu, lane_sum, off);

        if (lane == 0)
            out[(p0 + pl) * S_N + (s0 + w)] = lane_sum * (1.f / 16.f) + c0;
    }
}

// ---------------- launch ---------------------------------------------------
extern "C" void kernel_launch(void* const* d_in, const int* in_sizes, int n_in,
                              void* d_out, int out_size) {
    const float* sat   = (const float*)d_in[0];
    const float* pano  = (const float*)d_in[1];
    const float* in_w  = (const float*)d_in[2];
    const float* in_b  = (const float*)d_in[3];
    const float* out_w = (const float*)d_in[4];
    const float* out_b = (const float*)d_in[5];
    const float* op_w  = (const float*)d_in[6];
    const float* op_b  = (const float*)d_in[7];
    float* out = (float*)d_out;

    cudaFuncSetAttribute(attn_kernel, cudaFuncAttributeMaxDynamicSharedMemorySize, SMEM_BYTES);

    prep_kernel<<<8, 256>>>(in_w, in_b, out_w, out_b, op_w, op_b);
    proj_kernel<<<dim3(32, 4, 2), 256>>>(pano, sat, in_w, in_b);
    vw_kernel<<<256, 256>>>(sat);
    kt_kernel<<<S_N, 128>>>();
    attn_kernel<<<dim3(32, 48), 128, SMEM_BYTES>>>(out);
}

// round 7
// speedup vs baseline: 3.2172x; 1.4998x over previous
#include <cuda_runtime.h>
#include <cuda_bf16.h>
#include <cstdint>

#define P_N 96
#define S_N 128
#define HN  8
#define HDN 32
#define LN  16
#define EN  256

typedef unsigned long long u64;

__device__ __forceinline__ u64 fma2(u64 a, u64 b, u64 c) {
    u64 d;
    asm("fma.rn.f32x2 %0, %1, %2, %3;" : "=l"(d) : "l"(a), "l"(b), "l"(c));
    return d;
}
__device__ __forceinline__ u64 pack2(float x) {
    u64 d;
    unsigned r = __float_as_uint(x);
    asm("mov.b64 %0, {%1, %1};" : "=l"(d) : "r"(r));
    return d;
}
__device__ __forceinline__ uint32_t smem_u32(const void* p) {
    uint32_t a;
    asm("{ .reg .u64 t; cvta.to.shared.u64 t, %1; cvt.u32.u64 %0, t; }" : "=r"(a) : "l"(p));
    return a;
}

#define LDSM4(r0, r1, r2, r3, addr)                                          \
    asm volatile("ldmatrix.sync.aligned.m8n8.x4.shared.b16 {%0,%1,%2,%3}, [%4];" \
                 : "=r"(r0), "=r"(r1), "=r"(r2), "=r"(r3) : "r"(addr))

#define MMA16816(d, a, b)                                                    \
    asm volatile("mma.sync.aligned.m16n8k16.row.col.f32.bf16.bf16.f32 "      \
                 "{%0,%1,%2,%3}, {%4,%5,%6,%7}, {%8,%9}, {%0,%1,%2,%3};"     \
                 : "+f"((d)[0]), "+f"((d)[1]), "+f"((d)[2]), "+f"((d)[3])    \
                 : "r"((a)[0]), "r"((a)[1]), "r"((a)[2]), "r"((a)[3]),       \
                   "r"((b)[0]), "r"((b)[1]))

// ---------------- scratch (device globals; no allocation allowed) ----------
// g_qs/g_ks: per row (x, h, i|j): 64 bf16 = [hi(d0..31) | lo(d0..31)], as u32 pairs
__device__ uint32_t g_qs[P_N * HN * LN * 32];
__device__ uint32_t g_ks[S_N * HN * LN * 32];
__device__ float g_vw[S_N * HN * LN];        // [s][h][j]
__device__ float g_wvf[HN * EN];
__device__ float g_bvf[HN];
__device__ float g_c0;
__device__ float g_part[HN * P_N * S_N];     // per-head partial sums

// ---------------- prep: weff (per-head slice), Wvf, bvf, c0 ----------------
__global__ void __launch_bounds__(256) prep_kernel(
        const float* __restrict__ in_w, const float* __restrict__ in_b,
        const float* __restrict__ Wo,   const float* __restrict__ bo,
        const float* __restrict__ Wop,  const float* __restrict__ bop) {
    const int h = blockIdx.x;
    const int tid = threadIdx.x;
    __shared__ float sweff[HDN];

    {
        int d = tid >> 3, part = tid & 7;
        float a = 0.f;
        int obase = part * 32;
        #pragma unroll 8
        for (int o = 0; o < 32; ++o)
            a = fmaf(Wop[obase + o], Wo[(obase + o) * EN + h * HDN + d], a);
        a += __shfl_xor_sync(0xffffffffu, a, 1);
        a += __shfl_xor_sync(0xffffffffu, a, 2);
        a += __shfl_xor_sync(0xffffffffu, a, 4);
        if (part == 0) sweff[d] = a;
    }
    __syncthreads();
    {
        int e = tid;
        float acc = 0.f;
        #pragma unroll 8
        for (int d = 0; d < HDN; ++d)
            acc = fmaf(in_w[(2 * EN + h * HDN + d) * EN + e], sweff[d], acc);
        g_wvf[h * EN + e] = acc;
    }
    if (tid < 32) {
        float b = in_b[2 * EN + h * HDN + tid] * sweff[tid];
        #pragma unroll
        for (int off = 16; off > 0; off >>= 1)
            b += __shfl_xor_sync(0xffffffffu, b, off);
        if (tid == 0) g_bvf[h] = b;
    }
    if (h == 0) {
        __shared__ float red[EN];
        red[tid] = bo[tid] * Wop[tid];
        __syncthreads();
        for (int s = 128; s > 0; s >>= 1) {
            if (tid < s) red[tid] += red[tid + s];
            __syncthreads();
        }
        if (tid == 0) g_c0 = red[0] + bop[0];
    }
}

// ---------------- Q / K projection GEMM; epilogue emits hi/lo bf16 ---------
__global__ void __launch_bounds__(256) proj_kernel(const float* __restrict__ pano,
                                                   const float* __restrict__ sat,
                                                   const float* __restrict__ in_w,
                                                   const float* __restrict__ in_b) {
    const int z = blockIdx.z;
    const float* X;
    int rtiles, woff;
    if (z == 0) { X = pano; rtiles = 24; woff = 0;  }
    else        { X = sat;  rtiles = 32; woff = EN; }
    if (blockIdx.x >= rtiles) return;

    const int m0 = blockIdx.x * 64;
    const int n0 = blockIdx.y * 64;

    __shared__ __align__(16) float As[32][68];
    __shared__ __align__(16) float Ws[32][68];

    const int tid = threadIdx.x;
    const int tx = tid & 15, ty = tid >> 4;

    u64 acc2[4][2];
    #pragma unroll
    for (int i = 0; i < 4; ++i) { acc2[i][0] = 0ull; acc2[i][1] = 0ull; }

    for (int k0 = 0; k0 < EN; k0 += 32) {
        #pragma unroll
        for (int t = 0; t < 8; ++t) {
            int idx = tid + t * 256;
            int m = idx >> 5, kk = idx & 31;
            As[kk][m] = X[(m0 + m) * EN + k0 + kk];
            Ws[kk][m] = in_w[(woff + n0 + m) * EN + k0 + kk];
        }
        __syncthreads();
        #pragma unroll
        for (int kk = 0; kk < 32; ++kk) {
            float4 a = *(const float4*)&As[kk][ty * 4];
            ulonglong2 b2 = *(const ulonglong2*)&Ws[kk][tx * 4];
            const float av[4] = {a.x, a.y, a.z, a.w};
            #pragma unroll
            for (int i = 0; i < 4; ++i) {
                u64 aq = pack2(av[i]);
                acc2[i][0] = fma2(aq, b2.x, acc2[i][0]);
                acc2[i][1] = fma2(aq, b2.y, acc2[i][1]);
            }
        }
        __syncthreads();
    }

    #pragma unroll
    for (int i = 0; i < 4; ++i) {
        int row = m0 + ty * 4 + i;              // x*16 + (i|j)
        int xr = row >> 4, ri = row & 15;
        #pragma unroll
        for (int jp = 0; jp < 2; ++jp) {
            float2 v2 = *(float2*)&acc2[i][jp];
            int col0 = n0 + tx * 4 + jp * 2;    // even; pair within one head
            int h = col0 >> 5, d = col0 & 31;
            float va = v2.x + in_b[woff + col0];
            float vb = v2.y + in_b[woff + col0 + 1];
            if (z == 0) { va *= 0.17677669529663687f; vb *= 0.17677669529663687f; }
            __nv_bfloat16 ha = __float2bfloat16(va);
            __nv_bfloat16 hb = __float2bfloat16(vb);
            __nv_bfloat16 la = __float2bfloat16(va - __bfloat162float(ha));
            __nv_bfloat16 lb = __float2bfloat16(vb - __bfloat162float(hb));
            uint32_t hw = ((uint32_t)__bfloat16_as_ushort(hb) << 16) | __bfloat16_as_ushort(ha);
            uint32_t lw = ((uint32_t)__bfloat16_as_ushort(lb) << 16) | __bfloat16_as_ushort(la);
            int base = ((xr * HN + h) * LN + ri) * 32 + (d >> 1);
            if (z == 0) { g_qs[base] = hw; g_qs[base + 16] = lw; }
            else        { g_ks[base] = hw; g_ks[base + 16] = lw; }
        }
    }
}

// ---------------- vw[s,h,j] = sat[s,j,:] . Wvf[h,:] + bvf[h] ---------------
__global__ void __launch_bounds__(256) vw_kernel(const float* __restrict__ sat) {
    const int T = blockIdx.x * 256 + threadIdx.x;
    const int q = T & 3;
    const int h = (T >> 2) & 7;
    const int r = T >> 5;                       // 0..2047
    const float4* __restrict__ x = (const float4*)(sat + r * EN + q * 64);
    const float4* __restrict__ w = (const float4*)(g_wvf + h * EN + q * 64);
    float acc = 0.f;
    #pragma unroll
    for (int e4 = 0; e4 < 16; ++e4) {
        float4 a = __ldg(x + e4), b = __ldg(w + e4);
        acc = fmaf(a.x, b.x, acc);
        acc = fmaf(a.y, b.y, acc);
        acc = fmaf(a.z, b.z, acc);
        acc = fmaf(a.w, b.w, acc);
    }
    acc += __shfl_xor_sync(0xffffffffu, acc, 1);
    acc += __shfl_xor_sync(0xffffffffu, acc, 2);
    if (q == 0) {
        int s = r >> 4, j = r & 15;
        g_vw[s * (HN * LN) + h * LN + j] = acc + __ldg(g_bvf + h);
    }
}

// ---------------- HMMA attention: bf16 mma.sync, 3-term compensation -------
// grid = (8 s-groups, 12 p-octets, 8 heads). 128 threads = 4 warps.
// smem rows: 64 bf16 (hi|lo) padded to 144B -> conflict-free ldmatrix.
#define ROWB   144
#define QBASE  0
#define KBASE  18432                 // 128 rows * 144
#define VWBASE 55296                 // KBASE + 256*144
#define ASMEM_BYTES 56320            // VWBASE + 1024

__global__ void __launch_bounds__(128) attn_mma_kernel() {
    extern __shared__ __align__(16) char smx[];
    const uint32_t sb = smem_u32(smx);
    const int tid = threadIdx.x;
    const int warp = tid >> 5, lane = tid & 31;
    const int g = lane >> 2, t = lane & 3;
    const int h = blockIdx.z;
    const int p0 = blockIdx.y * 8;
    const int s0 = blockIdx.x * 16;

    // ---- stage Q: 8 panos x 16 i rows, 128B/row -> 144B rows ----
    {
        const uint4* __restrict__ src = (const uint4*)g_qs;
        #pragma unroll
        for (int tt = 0; tt < 8; ++tt) {
            int u = tid + tt * 128;            // 0..1023 = row*8 + chunk
            int row = u >> 3, ch = u & 7;
            int pp = row >> 4, ii = row & 15;
            uint4 v = src[(((p0 + pp) * HN + h) * LN + ii) * 8 + ch];
            *(uint4*)(smx + QBASE + row * ROWB + ch * 16) = v;
        }
    }
    // ---- stage K: 16 sats x 16 j rows ----
    {
        const uint4* __restrict__ src = (const uint4*)g_ks;
        #pragma unroll
        for (int tt = 0; tt < 16; ++tt) {
            int u = tid + tt * 128;            // 0..2047
            int row = u >> 3, ch = u & 7;
            int sp = row >> 4, jj = row & 15;
            uint4 v = src[(((s0 + sp) * HN + h) * LN + jj) * 8 + ch];
            *(uint4*)(smx + KBASE + row * ROWB + ch * 16) = v;
        }
    }
    // ---- stage vw [16 s'][16 j] ----
    {
        #pragma unroll
        for (int tt = 0; tt < 2; ++tt) {
            int u = tid + tt * 128;            // 0..255
            *(float*)(smx + VWBASE + u * 4) =
                g_vw[(s0 + (u >> 4)) * (HN * LN) + h * LN + (u & 15)];
        }
    }
    __syncthreads();

    const float* vws = (const float*)(smx + VWBASE);

    for (int iter = 0; iter < 4; ++iter) {
        // ---- load A fragments: 2 m16 tiles x 4 k16-blocks ----
        uint32_t A[2][4][4];
        #pragma unroll
        for (int m = 0; m < 2; ++m) {
            int R0 = iter * 32 + m * 16;
            uint32_t rowaddr = sb + QBASE + (R0 + (lane & 15)) * ROWB + ((lane >> 4) * 16);
            #pragma unroll
            for (int kb = 0; kb < 4; ++kb)
                LDSM4(A[m][kb][0], A[m][kb][1], A[m][kb][2], A[m][kb][3],
                      rowaddr + kb * 32);
        }

        #pragma unroll
        for (int npair = 0; npair < 4; ++npair) {
            // ---- load B fragments: 2 n8 tiles x 4 k16-blocks x 2 regs ----
            uint32_t Bf[2][4][2];
            #pragma unroll
            for (int nn = 0; nn < 2; ++nn) {
                int N0 = warp * 64 + (npair * 2 + nn) * 8;
                uint32_t rowaddr = sb + KBASE + (N0 + (lane & 7)) * ROWB + ((lane >> 3) * 16);
                LDSM4(Bf[nn][0][0], Bf[nn][0][1], Bf[nn][1][0], Bf[nn][1][1], rowaddr);
                LDSM4(Bf[nn][2][0], Bf[nn][2][1], Bf[nn][3][0], Bf[nn][3][1], rowaddr + 64);
            }

            float acc[2][2][4];
            #pragma unroll
            for (int m = 0; m < 2; ++m)
                #pragma unroll
                for (int nn = 0; nn < 2; ++nn)
                    #pragma unroll
                    for (int c = 0; c < 4; ++c) acc[m][nn][c] = 0.f;

            #pragma unroll
            for (int m = 0; m < 2; ++m)
                #pragma unroll
                for (int nn = 0; nn < 2; ++nn) {
                    MMA16816(acc[m][nn], A[m][0], Bf[nn][0]);  // qh.kh d0-15
                    MMA16816(acc[m][nn], A[m][1], Bf[nn][1]);  // qh.kh d16-31
                    MMA16816(acc[m][nn], A[m][0], Bf[nn][2]);  // qh.kl
                    MMA16816(acc[m][nn], A[m][1], Bf[nn][3]);
                    MMA16816(acc[m][nn], A[m][2], Bf[nn][0]);  // ql.kh
                    MMA16816(acc[m][nn], A[m][3], Bf[nn][1]);
                }

            // ---- epilogue: softmax over 16 j + vw dot, reduce over i ----
            int sl = warp * 4 + npair;                 // local sat
            float vw0 = vws[sl * 16 + 2 * t];
            float vw1 = vws[sl * 16 + 2 * t + 1];
            float vw2 = vws[sl * 16 + 2 * t + 8];
            float vw3 = vws[sl * 16 + 2 * t + 9];

            #pragma unroll
            for (int m = 0; m < 2; ++m) {
                float e0 = __expf(acc[m][0][0]);
                float e1 = __expf(acc[m][0][1]);
                float e2 = __expf(acc[m][1][0]);
                float e3 = __expf(acc[m][1][1]);
                float num = e0 * vw0 + e1 * vw1 + e2 * vw2 + e3 * vw3;
                float den = e0 + e1 + e2 + e3;
                float f0 = __expf(acc[m][0][2]);
                float f1 = __expf(acc[m][0][3]);
                float f2 = __expf(acc[m][1][2]);
                float f3 = __expf(acc[m][1][3]);
                float numh = f0 * vw0 + f1 * vw1 + f2 * vw2 + f3 * vw3;
                float denh = f0 + f1 + f2 + f3;

                num  += __shfl_xor_sync(0xffffffffu, num, 1);
                den  += __shfl_xor_sync(0xffffffffu, den, 1);
                numh += __shfl_xor_sync(0xffffffffu, numh, 1);
                denh += __shfl_xor_sync(0xffffffffu, denh, 1);
                num  += __shfl_xor_sync(0xffffffffu, num, 2);
                den  += __shfl_xor_sync(0xffffffffu, den, 2);
                numh += __shfl_xor_sync(0xffffffffu, numh, 2);
                denh += __shfl_xor_sync(0xffffffffu, denh, 2);

                float val = __fdividef(num, den) + __fdividef(numh, denh);
                val += __shfl_xor_sync(0xffffffffu, val, 4);
                val += __shfl_xor_sync(0xffffffffu, val, 8);
                val += __shfl_xor_sync(0xffffffffu, val, 16);

                if (lane == 0)
                    g_part[(h * P_N + p0 + iter * 2 + m) * S_N + s0 + sl] = val;
            }
        }
    }
}

// ---------------- final reduce over heads ----------------------------------
__global__ void __launch_bounds__(256) reduce_kernel(float* __restrict__ out) {
    int idx = blockIdx.x * 256 + threadIdx.x;
    if (idx >= P_N * S_N) return;
    float s = 0.f;
    #pragma unroll
    for (int h = 0; h < HN; ++h) s += g_part[h * (P_N * S_N) + idx];
    out[idx] = s * (1.f / 16.f) + g_c0;
}

// ---------------- launch ---------------------------------------------------
extern "C" void kernel_launch(void* const* d_in, const int* in_sizes, int n_in,
                              void* d_out, int out_size) {
    const float* sat   = (const float*)d_in[0];
    const float* pano  = (const float*)d_in[1];
    const float* in_w  = (const float*)d_in[2];
    const float* in_b  = (const float*)d_in[3];
    const float* out_w = (const float*)d_in[4];
    const float* out_b = (const float*)d_in[5];
    const float* op_w  = (const float*)d_in[6];
    const float* op_b  = (const float*)d_in[7];
    float* out = (float*)d_out;

    cudaFuncSetAttribute(attn_mma_kernel, cudaFuncAttributeMaxDynamicSharedMemorySize,
                         ASMEM_BYTES);

    prep_kernel<<<8, 256>>>(in_w, in_b, out_w, out_b, op_w, op_b);
    proj_kernel<<<dim3(32, 4, 2), 256>>>(pano, sat, in_w, in_b);
    vw_kernel<<<256, 256>>>(sat);
    attn_mma_kernel<<<dim3(8, 12, 8), 128, ASMEM_BYTES>>>();
    reduce_kernel<<<48, 256>>>(out);
}